// round 9
// baseline (speedup 1.0000x reference)
#include <cuda_runtime.h>
#include <cstdint>
#include <math.h>

#define NRE 8
#define XS 132     // plain x/h smem row stride (floats)

// ---- dynamic smem byte offsets ----
#define XF_OFF   0          // 65536: x A-frag [t8][k16][l32][4] tf32
#define HS_OFF   65536      // 67584: [128][132] fp32 x staging -> h (tf32) plain
#define WR_OFF   133120     // 65536: ring 2 x 32KB fused chunks
#define MGS_OFF  198656     // 4096: routing weights [128][8]
#define B1S_OFF  202752     // 5120
#define B2S_OFF  207872     // 5120
#define SMEM_BYTES 212992

// Fused weight stream: 44 steps (s = 4e+q, e=0..10, q=0..3), each 32KB (8192 floats):
//   [0..4096)    = W1_e quarter q   (paired B-frags [kl4][jp8][l32][4]), valid e<10
//   [4096..8192) = W2_{e-1} quarter q, valid e>=1
__device__ __align__(16) float g_wfrag[44 * 8192];

static __device__ __forceinline__ unsigned f2tf(float x) {
    unsigned u; asm("cvt.rna.tf32.f32 %0, %1;" : "=r"(u) : "f"(x)); return u;
}
static __device__ __forceinline__ float tf(float x) { return __uint_as_float(f2tf(x)); }
static __device__ __forceinline__ uint32_t s2u(const void* p) {
    uint32_t a;
    asm("{ .reg .u64 t; cvta.to.shared.u64 t, %1; cvt.u32.u64 %0, t; }" : "=r"(a) : "l"(p));
    return a;
}
static __device__ __forceinline__ void mma_tf32(float d[4], const unsigned a[4], const unsigned b[2]) {
    asm volatile(
        "mma.sync.aligned.m16n8k8.row.col.f32.tf32.tf32.f32 "
        "{%0,%1,%2,%3}, {%4,%5,%6,%7}, {%8,%9}, {%0,%1,%2,%3};"
        : "+f"(d[0]), "+f"(d[1]), "+f"(d[2]), "+f"(d[3])
        : "r"(a[0]), "r"(a[1]), "r"(a[2]), "r"(a[3]), "r"(b[0]), "r"(b[1]));
}
static __device__ __forceinline__ float gelu_f(float x) {
    float u = 0.7978845608028654f * (x + 0.044715f * x * x * x);
    float ex = __expf(2.0f * u);
    float t = 1.0f - 2.0f / (ex + 1.0f);       // tanh(u), inf-safe
    return 0.5f * x * (1.0f + t);
}
static __device__ __forceinline__ void cp16(uint32_t dst, const void* src) {
    asm volatile("cp.async.cg.shared.global [%0], [%1], 16;" :: "r"(dst), "l"(src) : "memory");
}
#define CP_COMMIT() asm volatile("cp.async.commit_group;" ::: "memory")
#define CP_WAIT1()  asm volatile("cp.async.wait_group 1;" ::: "memory")

// ============ prep: weights -> fused dual-stream, paired B-frag, tf32 ============
__global__ void __launch_bounds__(256, 1)
prep_kernel(const float* __restrict__ We1, const float* __restrict__ Ws1,
            const float* __restrict__ We2, const float* __restrict__ Ws2) {
    extern __shared__ float ws[];          // [128][132]
    int m = blockIdx.x;                    // 0..7 We1, 8..9 Ws1, 10..17 We2, 18..19 Ws2
    const float* W;
    int ee, isw2;
    if (m < 8)       { W = We1 + m * 16384;        ee = m;      isw2 = 0; }
    else if (m < 10) { W = Ws1 + (m - 8) * 16384;  ee = m;      isw2 = 0; }
    else if (m < 18) { W = We2 + (m - 10) * 16384; ee = m - 10; isw2 = 1; }
    else             { W = Ws2 + (m - 18) * 16384; ee = m - 10; isw2 = 1; }
    const int tid = threadIdx.x;
#pragma unroll
    for (int it = 0; it < 16; it++) {
        int idx = it * 256 + tid;
        int row = idx >> 5, c4 = (idx & 31) << 2;
        float4 v = *reinterpret_cast<const float4*>(W + row * 128 + c4);
        v.x = tf(v.x); v.y = tf(v.y); v.z = tf(v.z); v.w = tf(v.w);
        *reinterpret_cast<float4*>(ws + row * XS + c4) = v;
    }
    __syncthreads();
    float4* base4 = reinterpret_cast<float4*>(g_wfrag);
#pragma unroll
    for (int it = 0; it < 16; it++) {
        int i = it * 256 + tid;            // 0..4095 float4 entries of this matrix
        int l  = i & 31;
        int jp = (i >> 5) & 7;
        int kl = (i >> 8) & 3;
        int q  = i >> 10;
        int rem = i & 1023;                // kl*256 + jp*32 + l
        int g = l >> 2, c = l & 3;
        int k = 4 * q + kl;
        int colA = 16 * jp + g;
        float4 o;
        o.x = ws[(8 * k + c) * XS + colA];
        o.y = ws[(8 * k + c + 4) * XS + colA];
        o.z = ws[(8 * k + c) * XS + colA + 8];
        o.w = ws[(8 * k + c + 4) * XS + colA + 8];
        // W1_e -> step 4e+q first half; W2_e -> step 4(e+1)+q second half
        size_t dst = isw2 ? ((size_t)(4 * (ee + 1) + q) * 2048 + 1024 + rem)
                          : ((size_t)(4 * ee + q) * 2048 + rem);
        base4[dst] = o;
    }
}

// ---- one quarter (4 ksteps) of the dual stage ----
template <bool G1, bool G2>
static __device__ __forceinline__ void dual_quarter(
    const float4* __restrict__ xf, const float* __restrict__ hs,
    const float4* __restrict__ w4,
    int q, int t0, int mrow, int pb, int g, int c, int lane,
    float (&acc1)[2][8][4], float (&facc)[2][8][4]) {
#pragma unroll
    for (int kl = 0; kl < 4; kl++) {
        const int k = 4 * q + kl;
        unsigned ax[2][4], ah[2][4];
        if (G1) {
#pragma unroll
            for (int i = 0; i < 2; i++) {
                float4 av = xf[((t0 + i) * 16 + k) * 32 + lane];
                ax[i][0] = __float_as_uint(av.x); ax[i][1] = __float_as_uint(av.y);
                ax[i][2] = __float_as_uint(av.z); ax[i][3] = __float_as_uint(av.w);
            }
        }
        if (G2) {
#pragma unroll
            for (int i = 0; i < 2; i++) {
                const float* ap = hs + (mrow + i * 16 + g) * XS + k * 8 + c;
                ah[i][0] = __float_as_uint(ap[0]);
                ah[i][1] = __float_as_uint(ap[8 * XS]);
                ah[i][2] = __float_as_uint(ap[4]);
                ah[i][3] = __float_as_uint(ap[8 * XS + 4]);
            }
        }
#pragma unroll
        for (int p = 0; p < 4; p++) {
            const int bi = (kl * 8 + pb + p) * 32 + lane;
            if (G1) {
                float4 bv = w4[bi];
                unsigned b0[2] = { __float_as_uint(bv.x), __float_as_uint(bv.y) };
                unsigned b1[2] = { __float_as_uint(bv.z), __float_as_uint(bv.w) };
                mma_tf32(acc1[0][2 * p], ax[0], b0);
                mma_tf32(acc1[1][2 * p], ax[1], b0);
                mma_tf32(acc1[0][2 * p + 1], ax[0], b1);
                mma_tf32(acc1[1][2 * p + 1], ax[1], b1);
            }
            if (G2) {
                float4 bv = w4[1024 + bi];
                unsigned b0[2] = { __float_as_uint(bv.x), __float_as_uint(bv.y) };
                unsigned b1[2] = { __float_as_uint(bv.z), __float_as_uint(bv.w) };
                mma_tf32(facc[0][2 * p], ah[0], b0);
                mma_tf32(facc[1][2 * p], ah[1], b0);
                mma_tf32(facc[0][2 * p + 1], ah[0], b1);
                mma_tf32(facc[1][2 * p + 1], ah[1], b1);
            }
        }
    }
}

// ============ main fused kernel ============
__global__ void __launch_bounds__(256)
moe_kernel(const float* __restrict__ x,
           const float* __restrict__ Wr1, const float* __restrict__ br1,
           const float* __restrict__ Wr2, const float* __restrict__ br2,
           const float* __restrict__ be1, const float* __restrict__ be2,
           const float* __restrict__ bs1, const float* __restrict__ bs2,
           float* __restrict__ out) {
    extern __shared__ char smem[];
    const uint32_t sb = s2u(smem);
    float4* xf = (float4*)(smem + XF_OFF);
    float*  hs = (float*)(smem + HS_OFF);
    float*  mgs = (float*)(smem + MGS_OFF);
    float*  b1s = (float*)(smem + B1S_OFF);
    float*  b2s = (float*)(smem + B2S_OFF);
    float* rW1 = (float*)(smem + XF_OFF);      // router scratch overlays XF
    float* rb1 = rW1 + 2048;
    float* rW2 = rW1 + 2064;
    float* rb2 = rW1 + 2192;
    float* rfb = rW1 + 2208;

    const int tid  = threadIdx.x;
    const int lane = tid & 31;
    const int wid  = tid >> 5;
    const int g    = lane >> 2;
    const int c    = lane & 3;
    const int t0   = (wid >> 1) * 2;
    const int mrow = t0 * 16;
    const int pb   = (wid & 1) * 4;        // jp base (4 pairs = 64 cols)
    const int ncol = (wid & 1) * 64;
    const long base = (long)blockIdx.x * 128;

    auto issue = [&](int s) {
        const char* src = (const char*)g_wfrag + (size_t)s * 32768;
        uint32_t d = sb + WR_OFF + (uint32_t)(s & 1) * 32768u;
#pragma unroll
        for (int i = 0; i < 8; i++) {
            uint32_t o = (uint32_t)(tid + i * 256) * 16u;
            cp16(d + o, src + o);
        }
    };
    issue(0); CP_COMMIT();
    issue(1); CP_COMMIT();

    // ---- stage x (fp32) + biases + router weights ----
#pragma unroll
    for (int it = 0; it < 16; it++) {
        int idx = it * 256 + tid;
        int row = idx >> 5, c4 = (idx & 31) << 2;
        float4 v = *reinterpret_cast<const float4*>(x + (base + row) * 128 + c4);
        *reinterpret_cast<float4*>(hs + row * XS + c4) = v;
    }
    for (int i = tid; i < 1280; i += 256) b1s[i] = (i < 1024) ? be1[i] : bs1[i - 1024];
    for (int i = tid; i < 1280; i += 256) b2s[i] = (i < 1024) ? be2[i] : bs2[i - 1024];
    for (int i = tid; i < 2048; i += 256) rW1[i] = Wr1[i];
    if (tid < 16)  rb1[tid] = br1[tid];
    if (tid < 128) rW2[tid] = Wr2[tid];
    if (tid < 8)   rb2[tid] = br2[tid];
    __syncthreads();

    // ---- router stage 1 (fp32) ----
    {
        int tok = tid & 127, jfb = (tid >> 7) * 8;
        float rf[8];
#pragma unroll
        for (int j = 0; j < 8; j++) rf[j] = rb1[jfb + j];
        for (int h = 0; h < 128; h++) {
            float xv = hs[tok * XS + h];
#pragma unroll
            for (int j = 0; j < 8; j++) rf[j] += xv * rW1[h * 16 + jfb + j];
        }
#pragma unroll
        for (int j = 0; j < 8; j++) rfb[tok * 16 + jfb + j] = fmaxf(rf[j], 0.0f);
    }
    __syncthreads();
    // ---- router stage 2 ----
    if (tid < 128) {
        float lg[8];
#pragma unroll
        for (int e = 0; e < 8; e++) lg[e] = rb2[e];
#pragma unroll
        for (int r = 0; r < 16; r++) {
            float v = rfb[tid * 16 + r];
#pragma unroll
            for (int e = 0; e < 8; e++) lg[e] += v * rW2[r * 8 + e];
        }
        float mx = lg[0];
#pragma unroll
        for (int e = 1; e < 8; e++) mx = fmaxf(mx, lg[e]);
        float s = 0.0f, gt[8];
#pragma unroll
        for (int e = 0; e < 8; e++) { gt[e] = expf(lg[e] - mx); s += gt[e]; }
        float inv = 1.0f / s, msum = 0.0f;
#pragma unroll
        for (int e = 0; e < 8; e++) {
            float gv = gt[e] * inv;
            gv = (gv > 0.125f) ? gv : 0.0f;
            gt[e] = gv; msum += gv;
        }
        float innorm = 1.0f / (msum + 1e-8f);
#pragma unroll
        for (int e = 0; e < 8; e++) mgs[tid * 8 + e] = gt[e] * innorm;
    }
    __syncthreads();

    // ---- pack x -> XF A-frag layout, tf32; round HS x to tf32 in place ----
#pragma unroll
    for (int it = 0; it < 16; it++) {
        int i = it * 256 + tid;
        int l = i & 31, k = (i >> 5) & 15, t = i >> 9;
        int gg = l >> 2, cc = l & 3;
        const float* p0 = hs + (16 * t + gg) * XS + 8 * k + cc;
        float4 v;
        v.x = tf(p0[0]);
        v.y = tf(p0[8 * XS]);
        v.z = tf(p0[4]);
        v.w = tf(p0[8 * XS + 4]);
        xf[i] = v;
    }
    __syncthreads();

    float facc[2][8][4], acc1[2][8][4];
#pragma unroll
    for (int i = 0; i < 2; i++)
#pragma unroll
        for (int j = 0; j < 8; j++)
#pragma unroll
            for (int r = 0; r < 4; r++) { facc[i][j][r] = 0.0f; acc1[i][j][r] = 0.0f; }

    // ---- dual-stage loop: stage e = GEMM1_e + GEMM2_{e-1} ----
#pragma unroll 1
    for (int e = 0; e <= 10; e++) {
#pragma unroll 1
        for (int q = 0; q < 4; q++) {
            int s = 4 * e + q;
            CP_WAIT1(); __syncthreads();
            const float4* w4 = (const float4*)(smem + WR_OFF + (s & 1) * 32768);
            if (e == 0)
                dual_quarter<true, false>(xf, hs, w4, q, t0, mrow, pb, g, c, lane, acc1, facc);
            else if (e < 10)
                dual_quarter<true, true>(xf, hs, w4, q, t0, mrow, pb, g, c, lane, acc1, facc);
            else
                dual_quarter<false, true>(xf, hs, w4, q, t0, mrow, pb, g, c, lane, acc1, facc);
            __syncthreads();
            if (s + 2 < 44) issue(s + 2);
            CP_COMMIT();
        }
        // ---- epilogue of expert e: h_e = tf32(mg * gelu(acc1 + b1)) -> HS ----
        if (e < 10) {
            const float* b1 = b1s + e * 128;
#pragma unroll
            for (int i = 0; i < 2; i++)
#pragma unroll
                for (int j = 0; j < 8; j++)
#pragma unroll
                    for (int rr = 0; rr < 2; rr++) {
                        int row = mrow + i * 16 + g + rr * 8;
                        int col = ncol + j * 8 + 2 * c;
                        float w = (e < NRE) ? mgs[row * 8 + e] : 1.0f;
                        float v0 = acc1[i][j][rr * 2 + 0] + b1[col];
                        float v1 = acc1[i][j][rr * 2 + 1] + b1[col + 1];
                        float2 hv;
                        hv.x = tf(w * gelu_f(v0));
                        hv.y = tf(w * gelu_f(v1));
                        *reinterpret_cast<float2*>(hs + row * XS + col) = hv;
                        acc1[i][j][rr * 2 + 0] = 0.0f;
                        acc1[i][j][rr * 2 + 1] = 0.0f;
                    }
        }
        // next stage's loop-top __syncthreads publishes h_e before GEMM2_e reads it
    }

    // ---- writeout: facc + rank-10 bias correction ----
#pragma unroll
    for (int i = 0; i < 2; i++)
#pragma unroll
        for (int j = 0; j < 8; j++)
#pragma unroll
            for (int rr = 0; rr < 2; rr++) {
                int row = mrow + i * 16 + g + rr * 8;
                int col = ncol + j * 8 + 2 * c;
                float v0 = facc[i][j][rr * 2 + 0];
                float v1 = facc[i][j][rr * 2 + 1];
#pragma unroll
                for (int e = 0; e < NRE; e++) {
                    float w = mgs[row * 8 + e];
                    v0 += w * b2s[e * 128 + col];
                    v1 += w * b2s[e * 128 + col + 1];
                }
                v0 += b2s[8 * 128 + col] + b2s[9 * 128 + col];
                v1 += b2s[8 * 128 + col + 1] + b2s[9 * 128 + col + 1];
                *reinterpret_cast<float2*>(out + (base + row) * 128 + col) = make_float2(v0, v1);
            }
}

extern "C" void kernel_launch(void* const* d_in, const int* in_sizes, int n_in,
                              void* d_out, int out_size) {
    const float* x   = (const float*)d_in[0];
    const float* Wr1 = (const float*)d_in[1];
    const float* br1 = (const float*)d_in[2];
    const float* Wr2 = (const float*)d_in[3];
    const float* br2 = (const float*)d_in[4];
    const float* We1 = (const float*)d_in[5];
    const float* be1 = (const float*)d_in[6];
    const float* We2 = (const float*)d_in[7];
    const float* be2 = (const float*)d_in[8];
    const float* Ws1 = (const float*)d_in[9];
    const float* bs1 = (const float*)d_in[10];
    const float* Ws2 = (const float*)d_in[11];
    const float* bs2 = (const float*)d_in[12];
    float* out = (float*)d_out;

    size_t prep_smem = 128 * XS * sizeof(float);
    cudaFuncSetAttribute(prep_kernel, cudaFuncAttributeMaxDynamicSharedMemorySize, (int)prep_smem);
    prep_kernel<<<20, 256, prep_smem>>>(We1, Ws1, We2, Ws2);

    int ntok = in_sizes[0] / 128;
    int grid = ntok / 128;
    cudaFuncSetAttribute(moe_kernel, cudaFuncAttributeMaxDynamicSharedMemorySize, SMEM_BYTES);
    moe_kernel<<<grid, 256, SMEM_BYTES>>>(x, Wr1, br1, Wr2, br2,
                                          be1, be2, bs1, bs2, out);
}

// round 10
// speedup vs baseline: 1.0404x; 1.0404x over previous
#include <cuda_runtime.h>
#include <cstdint>
#include <math.h>

#define NRE 8
#define NEXP 10
#define XS 132     // plain x/h smem row stride (floats)

// ---- dynamic smem byte offsets (identical to R5) ----
#define XF_OFF   0          // 65536: x A-frag [t8][k16][l32][4] tf32
#define HS_OFF   65536      // 67584: [128][132] fp32 x staging -> h (tf32)
#define WR_OFF   133120     // 2 x 32768 weight ring, paired B-frag chunks [k8][jp8][l32][4]
#define MGS_OFF  198656     // 4096: routing weights [128][8]
#define B1S_OFF  202752     // 5120
#define B2S_OFF  207872     // 5120
#define SMEM_BYTES 212992

// Expert-interleaved paired-B-frag images: expert e at floats [e*32768,(e+1)*32768):
//   [+0 .. +16384)     = W1_e   [k16][jp8][l32][4]  (jp = pair of n8-tiles)
//   [+16384 .. +32768) = W2_e
// 32KB chunk c at byte c*32768: c = 4e+{0,1,2,3} = {W1h0, W1h1, W2h0, W2h1}.
__device__ __align__(16) float g_wfrag[20 * 16384];

// ---------------- helpers ----------------
static __device__ __forceinline__ unsigned f2tf(float x) {
    unsigned u; asm("cvt.rna.tf32.f32 %0, %1;" : "=r"(u) : "f"(x)); return u;
}
static __device__ __forceinline__ float tf(float x) { return __uint_as_float(f2tf(x)); }
static __device__ __forceinline__ uint32_t s2u(const void* p) {
    uint32_t a;
    asm("{ .reg .u64 t; cvta.to.shared.u64 t, %1; cvt.u32.u64 %0, t; }" : "=r"(a) : "l"(p));
    return a;
}
static __device__ __forceinline__ void mma_tf32(float d[4], const unsigned a[4], const unsigned b[2]) {
    asm volatile(
        "mma.sync.aligned.m16n8k8.row.col.f32.tf32.tf32.f32 "
        "{%0,%1,%2,%3}, {%4,%5,%6,%7}, {%8,%9}, {%0,%1,%2,%3};"
        : "+f"(d[0]), "+f"(d[1]), "+f"(d[2]), "+f"(d[3])
        : "r"(a[0]), "r"(a[1]), "r"(a[2]), "r"(a[3]), "r"(b[0]), "r"(b[1]));
}
static __device__ __forceinline__ float gelu_f(float x) {
    float u = 0.7978845608028654f * (x + 0.044715f * x * x * x);
    float ex = __expf(2.0f * u);
    float t = 1.0f - 2.0f / (ex + 1.0f);       // tanh(u), inf-safe
    return 0.5f * x * (1.0f + t);
}
static __device__ __forceinline__ void cp16(uint32_t dst, const void* src) {
    asm volatile("cp.async.cg.shared.global [%0], [%1], 16;" :: "r"(dst), "l"(src) : "memory");
}
#define CP_COMMIT() asm volatile("cp.async.commit_group;" ::: "memory")
#define CP_WAIT1()  asm volatile("cp.async.wait_group 1;" ::: "memory")

// ============ prep: rewrite weights into paired B-frag order, tf32-rounded ============
__global__ void __launch_bounds__(256, 1)
prep_kernel(const float* __restrict__ We1, const float* __restrict__ Ws1,
            const float* __restrict__ We2, const float* __restrict__ Ws2) {
    extern __shared__ float ws[];          // [128][132]
    int m = blockIdx.x;                    // 0..7 We1, 8..9 Ws1, 10..17 We2, 18..19 Ws2
    const float* W;
    int ee, isw2;
    if (m < 8)       { W = We1 + m * 16384;        ee = m;      isw2 = 0; }
    else if (m < 10) { W = Ws1 + (m - 8) * 16384;  ee = m;      isw2 = 0; }
    else if (m < 18) { W = We2 + (m - 10) * 16384; ee = m - 10; isw2 = 1; }
    else             { W = Ws2 + (m - 18) * 16384; ee = m - 10; isw2 = 1; }
    const int tid = threadIdx.x;
#pragma unroll
    for (int it = 0; it < 16; it++) {
        int idx = it * 256 + tid;          // float4 index
        int row = idx >> 5, c4 = (idx & 31) << 2;
        float4 v = *reinterpret_cast<const float4*>(W + row * 128 + c4);
        v.x = tf(v.x); v.y = tf(v.y); v.z = tf(v.z); v.w = tf(v.w);
        *reinterpret_cast<float4*>(ws + row * XS + c4) = v;
    }
    __syncthreads();
    float4* dst4 = reinterpret_cast<float4*>(g_wfrag + (size_t)ee * 32768 + (size_t)isw2 * 16384);
#pragma unroll
    for (int it = 0; it < 16; it++) {
        int i = it * 256 + tid;            // entry 0..4095: [k][jp][l]
        int l = i & 31, jp = (i >> 5) & 7, k = i >> 8;
        int g = l >> 2, c = l & 3;
        float4 o;
        o.x = ws[(8 * k + c) * XS + 16 * jp + g];          // b0 of j = 2jp
        o.y = ws[(8 * k + c + 4) * XS + 16 * jp + g];      // b1 of j = 2jp
        o.z = ws[(8 * k + c) * XS + 16 * jp + 8 + g];      // b0 of j = 2jp+1
        o.w = ws[(8 * k + c + 4) * XS + 16 * jp + 8 + g];  // b1 of j = 2jp+1
        dst4[i] = o;
    }
}

// ============ main fused kernel (R5 skeleton) ============
__global__ void __launch_bounds__(256, 1)
moe_kernel(const float* __restrict__ x,
           const float* __restrict__ Wr1, const float* __restrict__ br1,
           const float* __restrict__ Wr2, const float* __restrict__ br2,
           const float* __restrict__ be1, const float* __restrict__ be2,
           const float* __restrict__ bs1, const float* __restrict__ bs2,
           float* __restrict__ out) {
    extern __shared__ char smem[];
    const uint32_t sb = s2u(smem);
    float4* xf = (float4*)(smem + XF_OFF);
    float*  hs = (float*)(smem + HS_OFF);
    float*  mgs = (float*)(smem + MGS_OFF);
    float*  b1s = (float*)(smem + B1S_OFF);
    float*  b2s = (float*)(smem + B2S_OFF);
    // router scratch overlays XF (packed only after router completes)
    float* rW1 = (float*)(smem + XF_OFF);
    float* rb1 = rW1 + 2048;
    float* rW2 = rW1 + 2064;
    float* rb2 = rW1 + 2192;
    float* rfb = rW1 + 2208;

    const int tid  = threadIdx.x;
    const int lane = tid & 31;
    const int wid  = tid >> 5;
    const int g    = lane >> 2;
    const int c    = lane & 3;
    const int t0   = (wid >> 1) * 2;       // first 16-row tile of this warp
    const int mrow = t0 * 16;
    const int pb   = (wid & 1) * 4;        // first jp (4 pairs = 64 cols)
    const int ncol = (wid & 1) * 64;
    const long base = (long)blockIdx.x * 128;

    // ---- issue first two weight chunks immediately ----
    {
        const char* src0 = (const char*)g_wfrag;
        uint32_t d0 = sb + WR_OFF, d1 = sb + WR_OFF + 32768u;
#pragma unroll
        for (int i = 0; i < 8; i++) { uint32_t o = (uint32_t)(tid + i * 256) * 16u; cp16(d0 + o, src0 + o); }
        CP_COMMIT();
#pragma unroll
        for (int i = 0; i < 8; i++) { uint32_t o = (uint32_t)(tid + i * 256) * 16u; cp16(d1 + o, src0 + 32768 + o); }
        CP_COMMIT();
    }

    // ---- stage x tile (fp32) + biases + router weights ----
#pragma unroll
    for (int it = 0; it < 16; it++) {
        int idx = it * 256 + tid;
        int row = idx >> 5, c4 = (idx & 31) << 2;
        float4 v = *reinterpret_cast<const float4*>(x + (base + row) * 128 + c4);
        *reinterpret_cast<float4*>(hs + row * XS + c4) = v;
    }
    for (int i = tid; i < 1280; i += 256) b1s[i] = (i < 1024) ? be1[i] : bs1[i - 1024];
    for (int i = tid; i < 1280; i += 256) b2s[i] = (i < 1024) ? be2[i] : bs2[i - 1024];
    for (int i = tid; i < 2048; i += 256) rW1[i] = Wr1[i];
    if (tid < 16)  rb1[tid] = br1[tid];
    if (tid < 128) rW2[tid] = Wr2[tid];
    if (tid < 8)   rb2[tid] = br2[tid];
    __syncthreads();

    // ---- router stage 1 (fp32) ----
    {
        int tok = tid & 127, jfb = (tid >> 7) * 8;
        float rf[8];
#pragma unroll
        for (int j = 0; j < 8; j++) rf[j] = rb1[jfb + j];
        for (int h = 0; h < 128; h++) {
            float xv = hs[tok * XS + h];
#pragma unroll
            for (int j = 0; j < 8; j++) rf[j] += xv * rW1[h * 16 + jfb + j];
        }
#pragma unroll
        for (int j = 0; j < 8; j++) rfb[tok * 16 + jfb + j] = fmaxf(rf[j], 0.0f);
    }
    __syncthreads();
    // ---- router stage 2: softmax -> threshold -> renorm ----
    if (tid < 128) {
        float lg[8];
#pragma unroll
        for (int e = 0; e < 8; e++) lg[e] = rb2[e];
#pragma unroll
        for (int r = 0; r < 16; r++) {
            float v = rfb[tid * 16 + r];
#pragma unroll
            for (int e = 0; e < 8; e++) lg[e] += v * rW2[r * 8 + e];
        }
        float mx = lg[0];
#pragma unroll
        for (int e = 1; e < 8; e++) mx = fmaxf(mx, lg[e]);
        float s = 0.0f, gt[8];
#pragma unroll
        for (int e = 0; e < 8; e++) { gt[e] = expf(lg[e] - mx); s += gt[e]; }
        float inv = 1.0f / s, msum = 0.0f;
#pragma unroll
        for (int e = 0; e < 8; e++) {
            float gv = gt[e] * inv;
            gv = (gv > 0.125f) ? gv : 0.0f;
            gt[e] = gv; msum += gv;
        }
        float innorm = 1.0f / (msum + 1e-8f);
#pragma unroll
        for (int e = 0; e < 8; e++) mgs[tid * 8 + e] = gt[e] * innorm;
    }
    __syncthreads();            // router scratch in XF now dead

    // ---- pack x -> XF A-frag layout [t][k][l][4], tf32 ----
#pragma unroll
    for (int it = 0; it < 16; it++) {
        int i = it * 256 + tid;            // = (t*16+k)*32 + l
        int l = i & 31, k = (i >> 5) & 15, t = i >> 9;
        int gg = l >> 2, cc = l & 3;
        const float* p0 = hs + (16 * t + gg) * XS + 8 * k + cc;
        float4 v;
        v.x = tf(p0[0]);
        v.y = tf(p0[8 * XS]);
        v.z = tf(p0[4]);
        v.w = tf(p0[8 * XS + 4]);
        xf[i] = v;
    }
    __syncthreads();

    float facc[2][8][4];
#pragma unroll
    for (int i = 0; i < 2; i++)
#pragma unroll
        for (int j = 0; j < 8; j++)
#pragma unroll
            for (int r = 0; r < 4; r++) facc[i][j][r] = 0.0f;

    const float4* wr0 = (const float4*)(smem + WR_OFF);
    const float4* wr1 = (const float4*)(smem + WR_OFF + 32768);

    // ---- expert loop ----
    for (int e = 0; e < NEXP; e++) {
        float acc[2][8][4];
#pragma unroll
        for (int i = 0; i < 2; i++)
#pragma unroll
            for (int j = 0; j < 8; j++)
#pragma unroll
                for (int r = 0; r < 4; r++) acc[i][j][r] = 0.0f;

        // ===== GEMM1 half 0 (ksteps 0..7), weights in buf0 =====
        CP_WAIT1(); __syncthreads();
#pragma unroll
        for (int k = 0; k < 8; k++) {
            unsigned a[2][4];
#pragma unroll
            for (int i = 0; i < 2; i++) {
                float4 av = xf[((t0 + i) * 16 + k) * 32 + lane];
                a[i][0] = __float_as_uint(av.x); a[i][1] = __float_as_uint(av.y);
                a[i][2] = __float_as_uint(av.z); a[i][3] = __float_as_uint(av.w);
            }
#pragma unroll
            for (int p = 0; p < 4; p++) {
                float4 bv = wr0[(k * 8 + pb + p) * 32 + lane];
                unsigned b0[2] = { __float_as_uint(bv.x), __float_as_uint(bv.y) };
                unsigned b1r[2] = { __float_as_uint(bv.z), __float_as_uint(bv.w) };
                mma_tf32(acc[0][2 * p], a[0], b0);
                mma_tf32(acc[1][2 * p], a[1], b0);
                mma_tf32(acc[0][2 * p + 1], a[0], b1r);
                mma_tf32(acc[1][2 * p + 1], a[1], b1r);
            }
        }
        __syncthreads();
        {   // issue chunk 4e+2 (W2_e half0) -> buf0
            const char* src = (const char*)g_wfrag + (size_t)(4 * e + 2) * 32768;
            uint32_t d = sb + WR_OFF;
#pragma unroll
            for (int i = 0; i < 8; i++) { uint32_t o = (uint32_t)(tid + i * 256) * 16u; cp16(d + o, src + o); }
            CP_COMMIT();
        }

        // ===== GEMM1 half 1 (ksteps 8..15), weights in buf1 =====
        CP_WAIT1(); __syncthreads();
#pragma unroll
        for (int k = 0; k < 8; k++) {
            unsigned a[2][4];
#pragma unroll
            for (int i = 0; i < 2; i++) {
                float4 av = xf[((t0 + i) * 16 + 8 + k) * 32 + lane];
                a[i][0] = __float_as_uint(av.x); a[i][1] = __float_as_uint(av.y);
                a[i][2] = __float_as_uint(av.z); a[i][3] = __float_as_uint(av.w);
            }
#pragma unroll
            for (int p = 0; p < 4; p++) {
                float4 bv = wr1[(k * 8 + pb + p) * 32 + lane];
                unsigned b0[2] = { __float_as_uint(bv.x), __float_as_uint(bv.y) };
                unsigned b1r[2] = { __float_as_uint(bv.z), __float_as_uint(bv.w) };
                mma_tf32(acc[0][2 * p], a[0], b0);
                mma_tf32(acc[1][2 * p], a[1], b0);
                mma_tf32(acc[0][2 * p + 1], a[0], b1r);
                mma_tf32(acc[1][2 * p + 1], a[1], b1r);
            }
        }
        // ===== epilogue: h = tf32(mg * gelu(acc + b1)) -> HS =====
        const float* b1 = b1s + e * 128;
#pragma unroll
        for (int i = 0; i < 2; i++)
#pragma unroll
            for (int j = 0; j < 8; j++)
#pragma unroll
                for (int rr = 0; rr < 2; rr++) {
                    int row = mrow + i * 16 + g + rr * 8;
                    int col = ncol + j * 8 + 2 * c;
                    float w = (e < NRE) ? mgs[row * 8 + e] : 1.0f;
                    float v0 = acc[i][j][rr * 2 + 0] + b1[col];
                    float v1 = acc[i][j][rr * 2 + 1] + b1[col + 1];
                    float2 hv;
                    hv.x = tf(w * gelu_f(v0));
                    hv.y = tf(w * gelu_f(v1));
                    *reinterpret_cast<float2*>(hs + row * XS + col) = hv;
                }
        __syncthreads();
        {   // issue chunk 4e+3 (W2_e half1) -> buf1
            const char* src = (const char*)g_wfrag + (size_t)(4 * e + 3) * 32768;
            uint32_t d = sb + WR_OFF + 32768u;
#pragma unroll
            for (int i = 0; i < 8; i++) { uint32_t o = (uint32_t)(tid + i * 256) * 16u; cp16(d + o, src + o); }
            CP_COMMIT();
        }

        // ===== GEMM2 half 0 (ksteps 0..7), A = hs plain, weights buf0 =====
        CP_WAIT1(); __syncthreads();
#pragma unroll
        for (int k = 0; k < 8; k++) {
            const int kb = k * 8;
            unsigned a[2][4];
#pragma unroll
            for (int i = 0; i < 2; i++) {
                const float* ap = hs + (mrow + i * 16 + g) * XS + kb + c;
                a[i][0] = __float_as_uint(ap[0]);
                a[i][1] = __float_as_uint(ap[8 * XS]);
                a[i][2] = __float_as_uint(ap[4]);
                a[i][3] = __float_as_uint(ap[8 * XS + 4]);
            }
#pragma unroll
            for (int p = 0; p < 4; p++) {
                float4 bv = wr0[(k * 8 + pb + p) * 32 + lane];
                unsigned b0[2] = { __float_as_uint(bv.x), __float_as_uint(bv.y) };
                unsigned b1r[2] = { __float_as_uint(bv.z), __float_as_uint(bv.w) };
                mma_tf32(facc[0][2 * p], a[0], b0);
                mma_tf32(facc[1][2 * p], a[1], b0);
                mma_tf32(facc[0][2 * p + 1], a[0], b1r);
                mma_tf32(facc[1][2 * p + 1], a[1], b1r);
            }
        }
        __syncthreads();
        if (e < 9) {   // issue chunk 4e+4 (next W1 half0) -> buf0
            const char* src = (const char*)g_wfrag + (size_t)(4 * e + 4) * 32768;
            uint32_t d = sb + WR_OFF;
#pragma unroll
            for (int i = 0; i < 8; i++) { uint32_t o = (uint32_t)(tid + i * 256) * 16u; cp16(d + o, src + o); }
            CP_COMMIT();
        }

        // ===== GEMM2 half 1 (ksteps 8..15), weights buf1 =====
        CP_WAIT1(); __syncthreads();
#pragma unroll
        for (int k = 0; k < 8; k++) {
            const int kb = 64 + k * 8;
            unsigned a[2][4];
#pragma unroll
            for (int i = 0; i < 2; i++) {
                const float* ap = hs + (mrow + i * 16 + g) * XS + kb + c;
                a[i][0] = __float_as_uint(ap[0]);
                a[i][1] = __float_as_uint(ap[8 * XS]);
                a[i][2] = __float_as_uint(ap[4]);
                a[i][3] = __float_as_uint(ap[8 * XS + 4]);
            }
#pragma unroll
            for (int p = 0; p < 4; p++) {
                float4 bv = wr1[(k * 8 + pb + p) * 32 + lane];
                unsigned b0[2] = { __float_as_uint(bv.x), __float_as_uint(bv.y) };
                unsigned b1r[2] = { __float_as_uint(bv.z), __float_as_uint(bv.w) };
                mma_tf32(facc[0][2 * p], a[0], b0);
                mma_tf32(facc[1][2 * p], a[1], b0);
                mma_tf32(facc[0][2 * p + 1], a[0], b1r);
                mma_tf32(facc[1][2 * p + 1], a[1], b1r);
            }
        }
        __syncthreads();
        if (e < 9) {   // issue chunk 4e+5 (next W1 half1) -> buf1
            const char* src = (const char*)g_wfrag + (size_t)(4 * e + 5) * 32768;
            uint32_t d = sb + WR_OFF + 32768u;
#pragma unroll
            for (int i = 0; i < 8; i++) { uint32_t o = (uint32_t)(tid + i * 256) * 16u; cp16(d + o, src + o); }
            CP_COMMIT();
        }
    }

    // ---- writeout: facc + rank-10 bias correction ----
#pragma unroll
    for (int i = 0; i < 2; i++)
#pragma unroll
        for (int j = 0; j < 8; j++)
#pragma unroll
            for (int rr = 0; rr < 2; rr++) {
                int row = mrow + i * 16 + g + rr * 8;
                int col = ncol + j * 8 + 2 * c;
                float v0 = facc[i][j][rr * 2 + 0];
                float v1 = facc[i][j][rr * 2 + 1];
#pragma unroll
                for (int e = 0; e < NRE; e++) {
                    float w = mgs[row * 8 + e];
                    v0 += w * b2s[e * 128 + col];
                    v1 += w * b2s[e * 128 + col + 1];
                }
                v0 += b2s[8 * 128 + col] + b2s[9 * 128 + col];
                v1 += b2s[8 * 128 + col + 1] + b2s[9 * 128 + col + 1];
                *reinterpret_cast<float2*>(out + (base + row) * 128 + col) = make_float2(v0, v1);
            }
}

extern "C" void kernel_launch(void* const* d_in, const int* in_sizes, int n_in,
                              void* d_out, int out_size) {
    const float* x   = (const float*)d_in[0];
    const float* Wr1 = (const float*)d_in[1];
    const float* br1 = (const float*)d_in[2];
    const float* Wr2 = (const float*)d_in[3];
    const float* br2 = (const float*)d_in[4];
    const float* We1 = (const float*)d_in[5];
    const float* be1 = (const float*)d_in[6];
    const float* We2 = (const float*)d_in[7];
    const float* be2 = (const float*)d_in[8];
    const float* Ws1 = (const float*)d_in[9];
    const float* bs1 = (const float*)d_in[10];
    const float* Ws2 = (const float*)d_in[11];
    const float* bs2 = (const float*)d_in[12];
    float* out = (float*)d_out;

    size_t prep_smem = 128 * XS * sizeof(float);
    cudaFuncSetAttribute(prep_kernel, cudaFuncAttributeMaxDynamicSharedMemorySize, (int)prep_smem);
    prep_kernel<<<20, 256, prep_smem>>>(We1, Ws1, We2, Ws2);

    int ntok = in_sizes[0] / 128;
    int grid = ntok / 128;
    cudaFuncSetAttribute(moe_kernel, cudaFuncAttributeMaxDynamicSharedMemorySize, SMEM_BYTES);
    moe_kernel<<<grid, 256, SMEM_BYTES>>>(x, Wr1, br1, Wr2, br2,
                                          be1, be2, bs1, bs2, out);
}

// round 11
// speedup vs baseline: 1.3392x; 1.2872x over previous
#include <cuda_runtime.h>
#include <cstdint>
#include <math.h>

#define NRE 8
#define NEXP 10
#define XS 132     // plain x/h smem row stride (floats)

// ---- dynamic smem byte offsets (main kernel) ----
#define XF_OFF   0          // 65536: x in A-frag layout [t8][k16][l32][4] tf32
#define HS_OFF   65536      // 67584: [128][132] fp32 x staging -> h (tf32) for GEMM2
#define WR_OFF   133120     // 2 x 32768 weight ring, B-frag chunks [k8][j16][l32][2]
#define MGS_OFF  198656     // 4096: routing weights [128][8]
#define B1S_OFF  202752     // 5120: all expert b1 [10][128]
#define B2S_OFF  207872     // 5120: all expert b2 [10][128]
#define SMEM_BYTES 212992

// Expert-interleaved B-frag images: expert e occupies floats [e*32768, (e+1)*32768):
//   [e*32768 .. +16384)          = W1_e  ([k16][j16][l32][2], half-K chunk = 32KB contiguous)
//   [e*32768+16384 .. +32768)    = W2_e
// Chunk c (32KB) at byte offset c*32768: c = 4e+{0,1,2,3} = {W1h0, W1h1, W2h0, W2h1} of expert e.
__device__ __align__(16) float g_wfrag[20 * 16384];

// ---------------- helpers ----------------
static __device__ __forceinline__ unsigned f2tf(float x) {
    unsigned u; asm("cvt.rna.tf32.f32 %0, %1;" : "=r"(u) : "f"(x)); return u;
}
static __device__ __forceinline__ float tf(float x) { return __uint_as_float(f2tf(x)); }
static __device__ __forceinline__ uint32_t s2u(const void* p) {
    uint32_t a;
    asm("{ .reg .u64 t; cvta.to.shared.u64 t, %1; cvt.u32.u64 %0, t; }" : "=r"(a) : "l"(p));
    return a;
}
static __device__ __forceinline__ void mma_tf32(float d[4], const unsigned a[4], const unsigned b[2]) {
    asm volatile(
        "mma.sync.aligned.m16n8k8.row.col.f32.tf32.tf32.f32 "
        "{%0,%1,%2,%3}, {%4,%5,%6,%7}, {%8,%9}, {%0,%1,%2,%3};"
        : "+f"(d[0]), "+f"(d[1]), "+f"(d[2]), "+f"(d[3])
        : "r"(a[0]), "r"(a[1]), "r"(a[2]), "r"(a[3]), "r"(b[0]), "r"(b[1]));
}
static __device__ __forceinline__ float gelu_tanh(float x) {
    float x3 = x * x * x;
    float inner = 0.7978845608028654f * (x + 0.044715f * x3);
    return 0.5f * x * (1.0f + tanhf(inner));
}
static __device__ __forceinline__ void cp16(uint32_t dst, const void* src) {
    asm volatile("cp.async.cg.shared.global [%0], [%1], 16;" :: "r"(dst), "l"(src) : "memory");
}
#define CP_COMMIT() asm volatile("cp.async.commit_group;" ::: "memory")
#define CP_WAIT1()  asm volatile("cp.async.wait_group 1;" ::: "memory")

// ============ prep: rewrite weights into B-frag order, tf32-rounded ============
// 80 blocks: block bid handles matrix m = bid>>2, K-quarter q = bid&3 (rows [32q, 32q+32)).
__global__ void __launch_bounds__(256, 4)
prep_kernel(const float* __restrict__ We1, const float* __restrict__ Ws1,
            const float* __restrict__ We2, const float* __restrict__ Ws2) {
    extern __shared__ float ws[];          // [32][XS]
    int bid = blockIdx.x;
    int m = bid >> 2;                      // 0..7 We1, 8..9 Ws1, 10..17 We2, 18..19 Ws2
    int q = bid & 3;                       // K-quarter
    const float* W;
    int ee, isw2;
    if (m < 8)       { W = We1 + m * 16384;        ee = m;      isw2 = 0; }
    else if (m < 10) { W = Ws1 + (m - 8) * 16384;  ee = m;      isw2 = 0; }
    else if (m < 18) { W = We2 + (m - 10) * 16384; ee = m - 10; isw2 = 1; }
    else             { W = Ws2 + (m - 18) * 16384; ee = m - 10; isw2 = 1; }
    const float* Wq = W + (size_t)(32 * q) * 128;   // 32 rows of this quarter
    const int tid = threadIdx.x;
#pragma unroll
    for (int it = 0; it < 4; it++) {
        int idx = it * 256 + tid;          // float4 index, 0..1023
        int row = idx >> 5, c4 = (idx & 31) << 2;
        float4 v = *reinterpret_cast<const float4*>(Wq + row * 128 + c4);
        v.x = tf(v.x); v.y = tf(v.y); v.z = tf(v.z); v.w = tf(v.w);
        *reinterpret_cast<float4*>(ws + row * XS + c4) = v;
    }
    __syncthreads();
    // expert-interleaved destination: W1_e at e*32768 floats, W2_e at e*32768+16384
    float* dst = g_wfrag + (size_t)ee * 32768 + (size_t)isw2 * 16384;
#pragma unroll
    for (int it = 0; it < 8; it++) {
        int i = it * 256 + tid;            // local entry 0..2047: [kl4][j16][l32]
        int l = i & 31, j = (i >> 5) & 15, kl = i >> 9;
        int k = 4 * q + kl;
        int g = l >> 2, c = l & 3;
        float2 o;
        o.x = ws[(8 * kl + c) * XS + 8 * j + g];       // global row 8k+c = 32q + 8kl + c
        o.y = ws[(8 * kl + c + 4) * XS + 8 * j + g];
        *reinterpret_cast<float2*>(dst + (size_t)(k * 512 + j * 32 + l) * 2) = o;
    }
}

// ============ main fused kernel (byte-identical hot path to the 350.7us champion) ============
__global__ void __launch_bounds__(256, 1)
moe_kernel(const float* __restrict__ x,
           const float* __restrict__ Wr1, const float* __restrict__ br1,
           const float* __restrict__ Wr2, const float* __restrict__ br2,
           const float* __restrict__ be1, const float* __restrict__ be2,
           const float* __restrict__ bs1, const float* __restrict__ bs2,
           float* __restrict__ out) {
    extern __shared__ char smem[];
    const uint32_t sb = s2u(smem);
    float4* xf = (float4*)(smem + XF_OFF);
    float*  hs = (float*)(smem + HS_OFF);
    float*  mgs = (float*)(smem + MGS_OFF);
    float*  b1s = (float*)(smem + B1S_OFF);
    float*  b2s = (float*)(smem + B2S_OFF);
    // router scratch overlays XF (packed only after router completes)
    float* rW1 = (float*)(smem + XF_OFF);
    float* rb1 = rW1 + 2048;
    float* rW2 = rW1 + 2064;
    float* rb2 = rW1 + 2192;
    float* rfb = rW1 + 2208;

    const int tid  = threadIdx.x;
    const int lane = tid & 31;
    const int wid  = tid >> 5;
    const int g    = lane >> 2;
    const int c    = lane & 3;
    const int t0   = (wid >> 1) * 2;       // first 16-row tile of this warp
    const int mrow = t0 * 16;
    const int jb   = (wid & 1) * 8;        // first n8 tile
    const int ncol = jb * 8;
    const long base = (long)blockIdx.x * 128;

    // ---- issue first two weight chunks immediately (overlaps everything below) ----
    {
        const char* src0 = (const char*)g_wfrag;
        uint32_t d0 = sb + WR_OFF, d1 = sb + WR_OFF + 32768u;
#pragma unroll
        for (int i = 0; i < 8; i++) { uint32_t o = (uint32_t)(tid + i * 256) * 16u; cp16(d0 + o, src0 + o); }
        CP_COMMIT();
#pragma unroll
        for (int i = 0; i < 8; i++) { uint32_t o = (uint32_t)(tid + i * 256) * 16u; cp16(d1 + o, src0 + 32768 + o); }
        CP_COMMIT();
    }

    // ---- stage x tile (fp32) + biases + router weights ----
#pragma unroll
    for (int it = 0; it < 16; it++) {
        int idx = it * 256 + tid;
        int row = idx >> 5, c4 = (idx & 31) << 2;
        float4 v = *reinterpret_cast<const float4*>(x + (base + row) * 128 + c4);
        *reinterpret_cast<float4*>(hs + row * XS + c4) = v;
    }
    for (int i = tid; i < 1280; i += 256) b1s[i] = (i < 1024) ? be1[i] : bs1[i - 1024];
    for (int i = tid; i < 1280; i += 256) b2s[i] = (i < 1024) ? be2[i] : bs2[i - 1024];
    for (int i = tid; i < 2048; i += 256) rW1[i] = Wr1[i];
    if (tid < 16)  rb1[tid] = br1[tid];
    if (tid < 128) rW2[tid] = Wr2[tid];
    if (tid < 8)   rb2[tid] = br2[tid];
    __syncthreads();

    // ---- router stage 1 (fp32) ----
    {
        int tok = tid & 127, jfb = (tid >> 7) * 8;
        float rf[8];
#pragma unroll
        for (int j = 0; j < 8; j++) rf[j] = rb1[jfb + j];
        for (int h = 0; h < 128; h++) {
            float xv = hs[tok * XS + h];
#pragma unroll
            for (int j = 0; j < 8; j++) rf[j] += xv * rW1[h * 16 + jfb + j];
        }
#pragma unroll
        for (int j = 0; j < 8; j++) rfb[tok * 16 + jfb + j] = fmaxf(rf[j], 0.0f);
    }
    __syncthreads();
    // ---- router stage 2: softmax -> threshold -> renorm ----
    if (tid < 128) {
        float lg[8];
#pragma unroll
        for (int e = 0; e < 8; e++) lg[e] = rb2[e];
#pragma unroll
        for (int r = 0; r < 16; r++) {
            float v = rfb[tid * 16 + r];
#pragma unroll
            for (int e = 0; e < 8; e++) lg[e] += v * rW2[r * 8 + e];
        }
        float mx = lg[0];
#pragma unroll
        for (int e = 1; e < 8; e++) mx = fmaxf(mx, lg[e]);
        float s = 0.0f, gt[8];
#pragma unroll
        for (int e = 0; e < 8; e++) { gt[e] = expf(lg[e] - mx); s += gt[e]; }
        float inv = 1.0f / s, msum = 0.0f;
#pragma unroll
        for (int e = 0; e < 8; e++) {
            float gv = gt[e] * inv;
            gv = (gv > 0.125f) ? gv : 0.0f;
            gt[e] = gv; msum += gv;
        }
        float innorm = 1.0f / (msum + 1e-8f);
#pragma unroll
        for (int e = 0; e < 8; e++) mgs[tid * 8 + e] = gt[e] * innorm;
    }
    __syncthreads();            // router scratch in XF now dead

    // ---- pack x -> XF A-frag layout [t][k][l][4], tf32 ----
#pragma unroll
    for (int it = 0; it < 16; it++) {
        int i = it * 256 + tid;            // = (t*16+k)*32 + l
        int l = i & 31, k = (i >> 5) & 15, t = i >> 9;
        int gg = l >> 2, cc = l & 3;
        const float* p0 = hs + (16 * t + gg) * XS + 8 * k + cc;
        float4 v;
        v.x = tf(p0[0]);
        v.y = tf(p0[8 * XS]);
        v.z = tf(p0[4]);
        v.w = tf(p0[8 * XS + 4]);
        xf[i] = v;
    }
    __syncthreads();

    float facc[2][8][4];
#pragma unroll
    for (int i = 0; i < 2; i++)
#pragma unroll
        for (int j = 0; j < 8; j++)
#pragma unroll
            for (int r = 0; r < 4; r++) facc[i][j][r] = 0.0f;

    const float2* wr0 = (const float2*)(smem + WR_OFF);
    const float2* wr1 = (const float2*)(smem + WR_OFF + 32768);

    // ---- expert loop ----
    for (int e = 0; e < NEXP; e++) {
        float acc[2][8][4];
#pragma unroll
        for (int i = 0; i < 2; i++)
#pragma unroll
            for (int j = 0; j < 8; j++)
#pragma unroll
                for (int r = 0; r < 4; r++) acc[i][j][r] = 0.0f;

        // ===== GEMM1 half 0 (ksteps 0..7), weights in buf0 =====
        CP_WAIT1(); __syncthreads();
#pragma unroll
        for (int k = 0; k < 8; k++) {
            unsigned a[2][4];
#pragma unroll
            for (int i = 0; i < 2; i++) {
                float4 av = xf[((t0 + i) * 16 + k) * 32 + lane];
                a[i][0] = __float_as_uint(av.x); a[i][1] = __float_as_uint(av.y);
                a[i][2] = __float_as_uint(av.z); a[i][3] = __float_as_uint(av.w);
            }
#pragma unroll
            for (int j = 0; j < 8; j++) {
                float2 bv = wr0[(k * 16 + jb + j) * 32 + lane];
                unsigned b[2] = { __float_as_uint(bv.x), __float_as_uint(bv.y) };
                mma_tf32(acc[0][j], a[0], b);
                mma_tf32(acc[1][j], a[1], b);
            }
        }
        __syncthreads();
        {   // issue chunk 4e+2 (W2_e half0) -> buf0
            const char* src = (const char*)g_wfrag + (size_t)(4 * e + 2) * 32768;
            uint32_t d = sb + WR_OFF;
#pragma unroll
            for (int i = 0; i < 8; i++) { uint32_t o = (uint32_t)(tid + i * 256) * 16u; cp16(d + o, src + o); }
            CP_COMMIT();
        }

        // ===== GEMM1 half 1 (ksteps 8..15), weights in buf1 =====
        CP_WAIT1(); __syncthreads();
#pragma unroll
        for (int k = 0; k < 8; k++) {
            unsigned a[2][4];
#pragma unroll
            for (int i = 0; i < 2; i++) {
                float4 av = xf[((t0 + i) * 16 + 8 + k) * 32 + lane];
                a[i][0] = __float_as_uint(av.x); a[i][1] = __float_as_uint(av.y);
                a[i][2] = __float_as_uint(av.z); a[i][3] = __float_as_uint(av.w);
            }
#pragma unroll
            for (int j = 0; j < 8; j++) {
                float2 bv = wr1[(k * 16 + jb + j) * 32 + lane];
                unsigned b[2] = { __float_as_uint(bv.x), __float_as_uint(bv.y) };
                mma_tf32(acc[0][j], a[0], b);
                mma_tf32(acc[1][j], a[1], b);
            }
        }
        // ===== epilogue: h = tf32(mg * gelu(acc + b1)) -> HS =====
        const float* b1 = b1s + e * 128;
#pragma unroll
        for (int i = 0; i < 2; i++)
#pragma unroll
            for (int j = 0; j < 8; j++)
#pragma unroll
                for (int rr = 0; rr < 2; rr++) {
                    int row = mrow + i * 16 + g + rr * 8;
                    int col = ncol + j * 8 + 2 * c;
                    float w = (e < NRE) ? mgs[row * 8 + e] : 1.0f;
                    float v0 = acc[i][j][rr * 2 + 0] + b1[col];
                    float v1 = acc[i][j][rr * 2 + 1] + b1[col + 1];
                    float2 hv;
                    hv.x = tf(w * gelu_tanh(v0));
                    hv.y = tf(w * gelu_tanh(v1));
                    *reinterpret_cast<float2*>(hs + row * XS + col) = hv;
                }
        __syncthreads();
        {   // issue chunk 4e+3 (W2_e half1) -> buf1
            const char* src = (const char*)g_wfrag + (size_t)(4 * e + 3) * 32768;
            uint32_t d = sb + WR_OFF + 32768u;
#pragma unroll
            for (int i = 0; i < 8; i++) { uint32_t o = (uint32_t)(tid + i * 256) * 16u; cp16(d + o, src + o); }
            CP_COMMIT();
        }

        // ===== GEMM2 half 0 (ksteps 0..7), A = hs plain, weights buf0 =====
        CP_WAIT1(); __syncthreads();
#pragma unroll
        for (int k = 0; k < 8; k++) {
            const int kb = k * 8;
            unsigned a[2][4];
#pragma unroll
            for (int i = 0; i < 2; i++) {
                const float* ap = hs + (mrow + i * 16 + g) * XS + kb + c;
                a[i][0] = __float_as_uint(ap[0]);
                a[i][1] = __float_as_uint(ap[8 * XS]);
                a[i][2] = __float_as_uint(ap[4]);
                a[i][3] = __float_as_uint(ap[8 * XS + 4]);
            }
#pragma unroll
            for (int j = 0; j < 8; j++) {
                float2 bv = wr0[(k * 16 + jb + j) * 32 + lane];
                unsigned b[2] = { __float_as_uint(bv.x), __float_as_uint(bv.y) };
                mma_tf32(facc[0][j], a[0], b);
                mma_tf32(facc[1][j], a[1], b);
            }
        }
        __syncthreads();
        if (e < 9) {   // issue chunk 4e+4 (next W1 half0) -> buf0
            const char* src = (const char*)g_wfrag + (size_t)(4 * e + 4) * 32768;
            uint32_t d = sb + WR_OFF;
#pragma unroll
            for (int i = 0; i < 8; i++) { uint32_t o = (uint32_t)(tid + i * 256) * 16u; cp16(d + o, src + o); }
            CP_COMMIT();
        }

        // ===== GEMM2 half 1 (ksteps 8..15), weights buf1 =====
        CP_WAIT1(); __syncthreads();
#pragma unroll
        for (int k = 0; k < 8; k++) {
            const int kb = 64 + k * 8;
            unsigned a[2][4];
#pragma unroll
            for (int i = 0; i < 2; i++) {
                const float* ap = hs + (mrow + i * 16 + g) * XS + kb + c;
                a[i][0] = __float_as_uint(ap[0]);
                a[i][1] = __float_as_uint(ap[8 * XS]);
                a[i][2] = __float_as_uint(ap[4]);
                a[i][3] = __float_as_uint(ap[8 * XS + 4]);
            }
#pragma unroll
            for (int j = 0; j < 8; j++) {
                float2 bv = wr1[(k * 16 + jb + j) * 32 + lane];
                unsigned b[2] = { __float_as_uint(bv.x), __float_as_uint(bv.y) };
                mma_tf32(facc[0][j], a[0], b);
                mma_tf32(facc[1][j], a[1], b);
            }
        }
        __syncthreads();
        if (e < 9) {   // issue chunk 4e+5 (next W1 half1) -> buf1
            const char* src = (const char*)g_wfrag + (size_t)(4 * e + 5) * 32768;
            uint32_t d = sb + WR_OFF + 32768u;
#pragma unroll
            for (int i = 0; i < 8; i++) { uint32_t o = (uint32_t)(tid + i * 256) * 16u; cp16(d + o, src + o); }
            CP_COMMIT();
        }
    }

    // ---- writeout: facc + rank-10 bias correction ----
#pragma unroll
    for (int i = 0; i < 2; i++)
#pragma unroll
        for (int j = 0; j < 8; j++)
#pragma unroll
            for (int rr = 0; rr < 2; rr++) {
                int row = mrow + i * 16 + g + rr * 8;
                int col = ncol + j * 8 + 2 * c;
                float v0 = facc[i][j][rr * 2 + 0];
                float v1 = facc[i][j][rr * 2 + 1];
#pragma unroll
                for (int e = 0; e < NRE; e++) {
                    float w = mgs[row * 8 + e];
                    v0 += w * b2s[e * 128 + col];
                    v1 += w * b2s[e * 128 + col + 1];
                }
                v0 += b2s[8 * 128 + col] + b2s[9 * 128 + col];
                v1 += b2s[8 * 128 + col + 1] + b2s[9 * 128 + col + 1];
                *reinterpret_cast<float2*>(out + (base + row) * 128 + col) = make_float2(v0, v1);
            }
}

extern "C" void kernel_launch(void* const* d_in, const int* in_sizes, int n_in,
                              void* d_out, int out_size) {
    const float* x   = (const float*)d_in[0];
    const float* Wr1 = (const float*)d_in[1];
    const float* br1 = (const float*)d_in[2];
    const float* Wr2 = (const float*)d_in[3];
    const float* br2 = (const float*)d_in[4];
    const float* We1 = (const float*)d_in[5];
    const float* be1 = (const float*)d_in[6];
    const float* We2 = (const float*)d_in[7];
    const float* be2 = (const float*)d_in[8];
    const float* Ws1 = (const float*)d_in[9];
    const float* bs1 = (const float*)d_in[10];
    const float* Ws2 = (const float*)d_in[11];
    const float* bs2 = (const float*)d_in[12];
    float* out = (float*)d_out;

    size_t prep_smem = 32 * XS * sizeof(float);
    cudaFuncSetAttribute(prep_kernel, cudaFuncAttributeMaxDynamicSharedMemorySize, (int)prep_smem);
    prep_kernel<<<80, 256, prep_smem>>>(We1, Ws1, We2, Ws2);

    int ntok = in_sizes[0] / 128;
    int grid = ntok / 128;
    cudaFuncSetAttribute(moe_kernel, cudaFuncAttributeMaxDynamicSharedMemorySize, SMEM_BYTES);
    moe_kernel<<<grid, 256, SMEM_BYTES>>>(x, Wr1, br1, Wr2, br2,
                                          be1, be2, bs1, bs2, out);
}

// round 12
// speedup vs baseline: 2.0745x; 1.5490x over previous
#include <cuda_runtime.h>
#include <cuda_fp16.h>
#include <cstdint>
#include <math.h>

#define NRE 8
#define NEXP 10
#define XS 132     // fp32 x staging row stride (floats)
#define HSU 68     // h row stride in uints (136 halves)

// ---- dynamic smem byte offsets ----
#define XP_OFF   0          // 67584: fp32 x staging [128][132] (router + pack source)
#define XF_OFF   67584      // 32768: x A-frags fp16 [t8][k8][l32] uint4
#define HS_OFF   100352     // 34816: h fp16 [128][68] uints
#define WR_OFF   135168     // 65536: ring 2 x 32KB (buf0 = W1, buf1 = W2)
#define MGS_OFF  200704     // 4096
#define B1S_OFF  204800     // 5120
#define B2S_OFF  209920     // 5120
#define SMEM_BYTES 215040

// fp16 B-frag weight images: chunk c = 2e + {0:W1_e, 1:W2_e}, 32KB each.
// in-chunk: uint2 entry [(k8)*16 + j][l32] = { h2(W[16k+2c][n], W[16k+2c+1][n]),
//                                              h2(W[16k+2c+8][n], W[16k+2c+9][n]) }, n = 8j+g
__device__ __align__(16) uint2 g_wfrag[20 * 4096];

// ---------------- helpers ----------------
static __device__ __forceinline__ uint32_t s2u(const void* p) {
    uint32_t a;
    asm("{ .reg .u64 t; cvta.to.shared.u64 t, %1; cvt.u32.u64 %0, t; }" : "=r"(a) : "l"(p));
    return a;
}
static __device__ __forceinline__ unsigned h2u(__half2 h) {
    return *reinterpret_cast<unsigned*>(&h);
}
static __device__ __forceinline__ void mma_f16(float d[4], const unsigned a[4], const unsigned b[2]) {
    asm volatile(
        "mma.sync.aligned.m16n8k16.row.col.f32.f16.f16.f32 "
        "{%0,%1,%2,%3}, {%4,%5,%6,%7}, {%8,%9}, {%0,%1,%2,%3};"
        : "+f"(d[0]), "+f"(d[1]), "+f"(d[2]), "+f"(d[3])
        : "r"(a[0]), "r"(a[1]), "r"(a[2]), "r"(a[3]), "r"(b[0]), "r"(b[1]));
}
static __device__ __forceinline__ float gelu_tanh(float x) {
    float x3 = x * x * x;
    float inner = 0.7978845608028654f * (x + 0.044715f * x3);
    return 0.5f * x * (1.0f + tanhf(inner));
}
static __device__ __forceinline__ void cp16(uint32_t dst, const void* src) {
    asm volatile("cp.async.cg.shared.global [%0], [%1], 16;" :: "r"(dst), "l"(src) : "memory");
}
#define CP_COMMIT() asm volatile("cp.async.commit_group;" ::: "memory")
#define CP_WAIT1()  asm volatile("cp.async.wait_group 1;" ::: "memory")

// ============ prep: weights -> fp16 B-frag chunks (one matrix per block) ============
__global__ void __launch_bounds__(256, 1)
prep_kernel(const float* __restrict__ We1, const float* __restrict__ Ws1,
            const float* __restrict__ We2, const float* __restrict__ Ws2) {
    extern __shared__ float ws[];          // [128][132]
    int m = blockIdx.x;                    // 0..7 We1, 8..9 Ws1, 10..17 We2, 18..19 Ws2
    const float* W;
    int ee, isw2;
    if (m < 8)       { W = We1 + m * 16384;        ee = m;      isw2 = 0; }
    else if (m < 10) { W = Ws1 + (m - 8) * 16384;  ee = m;      isw2 = 0; }
    else if (m < 18) { W = We2 + (m - 10) * 16384; ee = m - 10; isw2 = 1; }
    else             { W = Ws2 + (m - 18) * 16384; ee = m - 10; isw2 = 1; }
    const int tid = threadIdx.x;
#pragma unroll
    for (int it = 0; it < 16; it++) {
        int idx = it * 256 + tid;
        int row = idx >> 5, c4 = (idx & 31) << 2;
        *reinterpret_cast<float4*>(ws + row * XS + c4) =
            *reinterpret_cast<const float4*>(W + row * 128 + c4);
    }
    __syncthreads();
    uint2* dst = g_wfrag + (size_t)(2 * ee + isw2) * 4096;
#pragma unroll
    for (int it = 0; it < 16; it++) {
        int i = it * 256 + tid;            // 0..4095: [k8][j16][l32]
        int l = i & 31, j = (i >> 5) & 15, k = i >> 9;
        int g = l >> 2, c = l & 3;
        int n = 8 * j + g;
        int r = 16 * k + 2 * c;
        __half2 lo = __floats2half2_rn(ws[r * XS + n],       ws[(r + 1) * XS + n]);
        __half2 hi = __floats2half2_rn(ws[(r + 8) * XS + n], ws[(r + 9) * XS + n]);
        uint2 o;
        o.x = h2u(lo);
        o.y = h2u(hi);
        dst[i] = o;
    }
}

// ============ main fused kernel ============
__global__ void __launch_bounds__(256, 1)
moe_kernel(const float* __restrict__ x,
           const float* __restrict__ Wr1, const float* __restrict__ br1,
           const float* __restrict__ Wr2, const float* __restrict__ br2,
           const float* __restrict__ be1, const float* __restrict__ be2,
           const float* __restrict__ bs1, const float* __restrict__ bs2,
           float* __restrict__ out) {
    extern __shared__ char smem[];
    const uint32_t sb = s2u(smem);
    float* xp  = (float*)(smem + XP_OFF);
    uint4* xfu = (uint4*)(smem + XF_OFF);
    unsigned* hsu = (unsigned*)(smem + HS_OFF);
    float* mgs = (float*)(smem + MGS_OFF);
    float* b1s = (float*)(smem + B1S_OFF);
    float* b2s = (float*)(smem + B2S_OFF);
    // router scratch overlays XF (packed only after router completes)
    float* rW1 = (float*)(smem + XF_OFF);
    float* rb1 = rW1 + 2048;
    float* rW2 = rW1 + 2064;
    float* rb2 = rW1 + 2192;
    float* rfb = rW1 + 2208;

    const int tid  = threadIdx.x;
    const int lane = tid & 31;
    const int wid  = tid >> 5;
    const int g    = lane >> 2;
    const int c    = lane & 3;
    const int t0   = (wid >> 1) * 2;       // first 16-row tile of this warp
    const int mrow = t0 * 16;
    const int jb   = (wid & 1) * 8;        // first n8 tile
    const int ncol = jb * 8;
    const long base = (long)blockIdx.x * 128;

    // ---- issue first two 32KB chunks (W1_0 -> buf0, W2_0 -> buf1) ----
    {
        const char* src0 = (const char*)g_wfrag;
        uint32_t d0 = sb + WR_OFF, d1 = sb + WR_OFF + 32768u;
#pragma unroll
        for (int i = 0; i < 8; i++) { uint32_t o = (uint32_t)(tid + i * 256) * 16u; cp16(d0 + o, src0 + o); }
        CP_COMMIT();
#pragma unroll
        for (int i = 0; i < 8; i++) { uint32_t o = (uint32_t)(tid + i * 256) * 16u; cp16(d1 + o, src0 + 32768 + o); }
        CP_COMMIT();
    }

    // ---- stage x (fp32) + biases + router weights ----
#pragma unroll
    for (int it = 0; it < 16; it++) {
        int idx = it * 256 + tid;
        int row = idx >> 5, c4 = (idx & 31) << 2;
        float4 v = *reinterpret_cast<const float4*>(x + (base + row) * 128 + c4);
        *reinterpret_cast<float4*>(xp + row * XS + c4) = v;
    }
    for (int i = tid; i < 1280; i += 256) b1s[i] = (i < 1024) ? be1[i] : bs1[i - 1024];
    for (int i = tid; i < 1280; i += 256) b2s[i] = (i < 1024) ? be2[i] : bs2[i - 1024];
    for (int i = tid; i < 2048; i += 256) rW1[i] = Wr1[i];
    if (tid < 16)  rb1[tid] = br1[tid];
    if (tid < 128) rW2[tid] = Wr2[tid];
    if (tid < 8)   rb2[tid] = br2[tid];
    __syncthreads();

    // ---- router stage 1 (fp32, full precision) ----
    {
        int tok = tid & 127, jfb = (tid >> 7) * 8;
        float rf[8];
#pragma unroll
        for (int j = 0; j < 8; j++) rf[j] = rb1[jfb + j];
        for (int h = 0; h < 128; h++) {
            float xv = xp[tok * XS + h];
#pragma unroll
            for (int j = 0; j < 8; j++) rf[j] += xv * rW1[h * 16 + jfb + j];
        }
#pragma unroll
        for (int j = 0; j < 8; j++) rfb[tok * 16 + jfb + j] = fmaxf(rf[j], 0.0f);
    }
    __syncthreads();
    // ---- router stage 2: softmax -> threshold -> renorm ----
    if (tid < 128) {
        float lg[8];
#pragma unroll
        for (int e = 0; e < 8; e++) lg[e] = rb2[e];
#pragma unroll
        for (int r = 0; r < 16; r++) {
            float v = rfb[tid * 16 + r];
#pragma unroll
            for (int e = 0; e < 8; e++) lg[e] += v * rW2[r * 8 + e];
        }
        float mx = lg[0];
#pragma unroll
        for (int e = 1; e < 8; e++) mx = fmaxf(mx, lg[e]);
        float s = 0.0f, gt[8];
#pragma unroll
        for (int e = 0; e < 8; e++) { gt[e] = expf(lg[e] - mx); s += gt[e]; }
        float inv = 1.0f / s, msum = 0.0f;
#pragma unroll
        for (int e = 0; e < 8; e++) {
            float gv = gt[e] * inv;
            gv = (gv > 0.125f) ? gv : 0.0f;
            gt[e] = gv; msum += gv;
        }
        float innorm = 1.0f / (msum + 1e-8f);
#pragma unroll
        for (int e = 0; e < 8; e++) mgs[tid * 8 + e] = gt[e] * innorm;
    }
    __syncthreads();            // router scratch in XF now dead

    // ---- pack x -> XF fp16 A-frags [t8][k8][l32] uint4 ----
#pragma unroll
    for (int it = 0; it < 8; it++) {
        int i = it * 256 + tid;            // = (t*8+k)*32 + l
        int l = i & 31, k = (i >> 5) & 7, t = i >> 8;
        int gg = l >> 2, cc = l & 3;
        const float* p0 = xp + (16 * t + gg) * XS + 16 * k + 2 * cc;
        uint4 v;
        v.x = h2u(__floats2half2_rn(p0[0], p0[1]));                       // row g,   k 2c..2c+1
        v.y = h2u(__floats2half2_rn(p0[8 * XS], p0[8 * XS + 1]));         // row g+8
        v.z = h2u(__floats2half2_rn(p0[8], p0[9]));                       // row g,   k 2c+8..2c+9
        v.w = h2u(__floats2half2_rn(p0[8 * XS + 8], p0[8 * XS + 9]));     // row g+8
        xfu[i] = v;
    }
    __syncthreads();

    float facc[2][8][4];
#pragma unroll
    for (int i = 0; i < 2; i++)
#pragma unroll
        for (int j = 0; j < 8; j++)
#pragma unroll
            for (int r = 0; r < 4; r++) facc[i][j][r] = 0.0f;

    const uint2* wr0 = (const uint2*)(smem + WR_OFF);           // W1 chunk
    const uint2* wr1 = (const uint2*)(smem + WR_OFF + 32768);   // W2 chunk

    // ---- expert loop: 2 chunks / 4 syncs per expert ----
    for (int e = 0; e < NEXP; e++) {
        float acc[2][8][4];
#pragma unroll
        for (int i = 0; i < 2; i++)
#pragma unroll
            for (int j = 0; j < 8; j++)
#pragma unroll
                for (int r = 0; r < 4; r++) acc[i][j][r] = 0.0f;

        // ===== GEMM1: 8 ksteps (k16 each), weights buf0 =====
        CP_WAIT1(); __syncthreads();       // chunk 2e (W1_e) ready
#pragma unroll
        for (int k = 0; k < 8; k++) {
            unsigned a[2][4];
#pragma unroll
            for (int i = 0; i < 2; i++) {
                uint4 av = xfu[((t0 + i) * 8 + k) * 32 + lane];
                a[i][0] = av.x; a[i][1] = av.y; a[i][2] = av.z; a[i][3] = av.w;
            }
#pragma unroll
            for (int j = 0; j < 8; j++) {
                uint2 bv = wr0[(k * 16 + jb + j) * 32 + lane];
                unsigned b[2] = { bv.x, bv.y };
                mma_f16(acc[0][j], a[0], b);
                mma_f16(acc[1][j], a[1], b);
            }
        }
        __syncthreads();                   // buf0 consumed
        if (e < 9) {                       // issue chunk 2e+2 (W1_{e+1}) -> buf0
            const char* src = (const char*)g_wfrag + (size_t)(2 * e + 2) * 32768;
            uint32_t d = sb + WR_OFF;
#pragma unroll
            for (int i = 0; i < 8; i++) { uint32_t o = (uint32_t)(tid + i * 256) * 16u; cp16(d + o, src + o); }
        }
        CP_COMMIT();

        // ===== epilogue: h = fp16(mg * gelu(acc + b1)) -> HS =====
        {
            const float* b1 = b1s + e * 128;
#pragma unroll
            for (int i = 0; i < 2; i++)
#pragma unroll
                for (int j = 0; j < 8; j++)
#pragma unroll
                    for (int rr = 0; rr < 2; rr++) {
                        int row = mrow + i * 16 + g + rr * 8;
                        int col = ncol + j * 8 + 2 * c;
                        float w = (e < NRE) ? mgs[row * 8 + e] : 1.0f;
                        float v0 = acc[i][j][rr * 2 + 0] + b1[col];
                        float v1 = acc[i][j][rr * 2 + 1] + b1[col + 1];
                        hsu[row * HSU + (col >> 1)] =
                            h2u(__floats2half2_rn(w * gelu_tanh(v0), w * gelu_tanh(v1)));
                    }
        }
        CP_WAIT1(); __syncthreads();       // chunk 2e+1 (W2_e) ready AND h published

        // ===== GEMM2: 8 ksteps, A = h fp16 plain, weights buf1, accumulate facc =====
#pragma unroll
        for (int k = 0; k < 8; k++) {
            unsigned a[2][4];
#pragma unroll
            for (int i = 0; i < 2; i++) {
                const unsigned* hp = hsu + (mrow + i * 16 + g) * HSU + 8 * k + c;
                a[i][0] = hp[0];               // row g,   k 2c..2c+1
                a[i][1] = hp[8 * HSU];         // row g+8
                a[i][2] = hp[4];               // row g,   k 2c+8..2c+9
                a[i][3] = hp[8 * HSU + 4];     // row g+8
            }
#pragma unroll
            for (int j = 0; j < 8; j++) {
                uint2 bv = wr1[(k * 16 + jb + j) * 32 + lane];
                unsigned b[2] = { bv.x, bv.y };
                mma_f16(facc[0][j], a[0], b);
                mma_f16(facc[1][j], a[1], b);
            }
        }
        __syncthreads();                   // buf1 consumed + all h reads done
        if (e < 9) {                       // issue chunk 2e+3 (W2_{e+1}) -> buf1
            const char* src = (const char*)g_wfrag + (size_t)(2 * e + 3) * 32768;
            uint32_t d = sb + WR_OFF + 32768u;
#pragma unroll
            for (int i = 0; i < 8; i++) { uint32_t o = (uint32_t)(tid + i * 256) * 16u; cp16(d + o, src + o); }
        }
        CP_COMMIT();
    }

    // ---- writeout: facc + rank-10 bias correction ----
#pragma unroll
    for (int i = 0; i < 2; i++)
#pragma unroll
        for (int j = 0; j < 8; j++)
#pragma unroll
            for (int rr = 0; rr < 2; rr++) {
                int row = mrow + i * 16 + g + rr * 8;
                int col = ncol + j * 8 + 2 * c;
                float v0 = facc[i][j][rr * 2 + 0];
                float v1 = facc[i][j][rr * 2 + 1];
#pragma unroll
                for (int e = 0; e < NRE; e++) {
                    float w = mgs[row * 8 + e];
                    v0 += w * b2s[e * 128 + col];
                    v1 += w * b2s[e * 128 + col + 1];
                }
                v0 += b2s[8 * 128 + col] + b2s[9 * 128 + col];
                v1 += b2s[8 * 128 + col + 1] + b2s[9 * 128 + col + 1];
                *reinterpret_cast<float2*>(out + (base + row) * 128 + col) = make_float2(v0, v1);
            }
}

extern "C" void kernel_launch(void* const* d_in, const int* in_sizes, int n_in,
                              void* d_out, int out_size) {
    const float* x   = (const float*)d_in[0];
    const float* Wr1 = (const float*)d_in[1];
    const float* br1 = (const float*)d_in[2];
    const float* Wr2 = (const float*)d_in[3];
    const float* br2 = (const float*)d_in[4];
    const float* We1 = (const float*)d_in[5];
    const float* be1 = (const float*)d_in[6];
    const float* We2 = (const float*)d_in[7];
    const float* be2 = (const float*)d_in[8];
    const float* Ws1 = (const float*)d_in[9];
    const float* bs1 = (const float*)d_in[10];
    const float* Ws2 = (const float*)d_in[11];
    const float* bs2 = (const float*)d_in[12];
    float* out = (float*)d_out;

    size_t prep_smem = 128 * XS * sizeof(float);
    cudaFuncSetAttribute(prep_kernel, cudaFuncAttributeMaxDynamicSharedMemorySize, (int)prep_smem);
    prep_kernel<<<20, 256, prep_smem>>>(We1, Ws1, We2, Ws2);

    int ntok = in_sizes[0] / 128;
    int grid = ntok / 128;
    cudaFuncSetAttribute(moe_kernel, cudaFuncAttributeMaxDynamicSharedMemorySize, SMEM_BYTES);
    moe_kernel<<<grid, 256, SMEM_BYTES>>>(x, Wr1, br1, Wr2, br2,
                                          be1, be2, bs1, bs2, out);
}